// round 2
// baseline (speedup 1.0000x reference)
#include <cuda_runtime.h>
#include <math.h>

// ---------------- problem constants ----------------
#define BATCH 4
#define INC   32
#define OUTC  64
#define HW    56
#define PH    58          // padded spatial (56 + 2*1)
#define MTOT  (BATCH*HW*HW)      // 12544 output pixels
#define FEAT_CF 256              // 32 channels * 8 bases, channels-last
#define FEAT_SZ (BATCH*PH*PH*FEAT_CF)   // 3,444,736 floats
#define XP_SZ   (BATCH*PH*PH*INC)       // 430,592 floats
#define KSPL  2304               // 9 taps * 256
#define KBAS  288                // 9 taps * 32
#define SPLITK 3                 // 2304 / 3 = 768 = 48 chunks of 16

// ---------------- scratch (device globals: allocation-free) ----------------
__device__ float g_feat[FEAT_SZ];            // padded basis features [b][h][w][c*8+f]
__device__ float g_xp[XP_SZ];                // padded raw x          [b][h][w][c]
__device__ float g_wps[KSPL*OUTC];           // packed spline weights [k][o]
__device__ float g_wpb[KBAS*OUTC];           // packed base weights   [k][o]
__device__ float g_S[SPLITK*MTOT*OUTC];      // split-K partials      [z][m][o]

// ---------------- knot helpers (match reference fp32 grid) ----------------
__device__ __forceinline__ float knot(int i) {
    // grid[j] = (j-3)*0.4f - 1.0f, j = 0..11  (knots -2.2 .. 2.2)
    return (float)(i - 3) * 0.4f - 1.0f;
}

// Cox-de Boor cubic bases at xv -> bb[0..7]; identical fp32 op order to reference.
__device__ __forceinline__ void bspline8(float xv, float* out8) {
    float bb[11];
#pragma unroll
    for (int i = 0; i < 11; i++)
        bb[i] = (xv >= knot(i) && xv < knot(i + 1)) ? 1.0f : 0.0f;
#pragma unroll
    for (int k = 1; k <= 3; k++) {
#pragma unroll
        for (int i = 0; i < 11; i++) {
            if (i < 11 - k) {
                float dl = fmaxf(knot(i + k) - knot(i), 1e-8f);
                float dr = fmaxf(knot(i + k + 1) - knot(i + 1), 1e-8f);
                bb[i] = (xv - knot(i)) / dl * bb[i] + (knot(i + k + 1) - xv) / dr * bb[i + 1];
            }
        }
    }
#pragma unroll
    for (int i = 0; i < 8; i++) out8[i] = bb[i];
}

// ---------------- kernel 1: pack weights ----------------
// g_wps[(tap*256 + c*8 + f)*64 + o] = spline_weight[o][c*9+tap][f]
// g_wpb[(tap*32  + c      )*64 + o] = base_weight[o][c][kh][kw], tap = kh*3+kw
__global__ void pack_kernel(const float* __restrict__ sw, const float* __restrict__ bw)
{
    int t = blockIdx.x * blockDim.x + threadIdx.x;
    const int NS = KSPL * OUTC;
    const int NB = KBAS * OUTC;
    if (t < NS) {
        int o = t & 63;
        int k = t >> 6;
        int tap = k >> 8;
        int cf  = k & 255;
        int c = cf >> 3, f = cf & 7;
        g_wps[k * 64 + o] = sw[(o * 288 + c * 9 + tap) * 8 + f];
    } else if (t < NS + NB) {
        int u = t - NS;
        int o = u & 63;
        int k = u >> 6;
        int tap = k >> 5;
        int c   = k & 31;
        g_wpb[k * 64 + o] = bw[(o * 32 + c) * 9 + tap];
    }
}

// ---------------- kernel 2: init padded scratch ----------------
// IMPORTANT: the reference unfolds zero-padded x and applies the B-spline basis
// to the padded zeros too. bases(0) != 0 (partition of unity). So g_feat must be
// initialized with the bases(0) pattern everywhere (interior is overwritten by
// fill_kernel); g_xp padding is true zero (conv semantics).
__global__ void init_kernel()
{
    float b0[8];
    bspline8(0.0f, b0);
    float4 v0 = make_float4(b0[0], b0[1], b0[2], b0[3]);
    float4 v1 = make_float4(b0[4], b0[5], b0[6], b0[7]);

    const int NF4 = FEAT_SZ / 4;
    const int NX4 = XP_SZ / 4;
    int stride = gridDim.x * blockDim.x;
    for (int i = blockIdx.x * blockDim.x + threadIdx.x; i < NF4 + NX4; i += stride) {
        if (i < NF4) ((float4*)g_feat)[i] = (i & 1) ? v1 : v0;   // 8-float period
        else         ((float4*)g_xp)[i - NF4] = make_float4(0.f, 0.f, 0.f, 0.f);
    }
}

// ---------------- kernel 3: B-spline basis fill (once per input pixel) ----------------
__global__ void fill_kernel(const float* __restrict__ x)
{
    int t = blockIdx.x * blockDim.x + threadIdx.x;
    if (t >= BATCH * INC * HW * HW) return;
    int c = t & 31;
    int rest = t >> 5;           // (b*56 + h)*56 + w
    int w = rest % 56;
    int r2 = rest / 56;
    int h = r2 % 56;
    int b = r2 / 56;

    float xv = x[((b * 32 + c) * 56 + h) * 56 + w];

    float bb[8];
    bspline8(xv, bb);

    int pBase = (b * 58 + h + 1) * 58 + (w + 1);
    float* fp = g_feat + (size_t)pBase * 256 + c * 8;
    *(float4*)(fp)     = make_float4(bb[0], bb[1], bb[2], bb[3]);
    *(float4*)(fp + 4) = make_float4(bb[4], bb[5], bb[6], bb[7]);
    g_xp[(size_t)pBase * 32 + c] = xv;
}

// ---------------- kernel 4: spline GEMM, M=12544 N=64 K=2304, split-K=3 ----------------
// 64x64 tile, BK=16, 128 threads, 8x4 micro-tile. A is implicit im2col over g_feat.
__global__ void __launch_bounds__(128) spline_gemm_kernel()
{
    __shared__ float As[16][64];
    __shared__ float Bs[16][64];

    const int tid   = threadIdx.x;
    const int mBase = blockIdx.x * 64;
    const int z     = blockIdx.z;
    const int ty = tid >> 4;          // 0..7  -> 8 M-rows
    const int tx = tid & 15;          // 0..15 -> 4 N-cols
    const int aRow = tid >> 2;        // 0..31 (two passes -> 64 rows)
    const int aq   = (tid & 3) << 2;  // k sub-offset 0/4/8/12

    // per-thread A row base offsets into g_feat (pixel -> padded coords)
    int rb[2];
#pragma unroll
    for (int p = 0; p < 2; p++) {
        int r = mBase + aRow + 32 * p;
        int b = r / 3136; int rem = r - b * 3136;
        int oh = rem / 56; int ow = rem - oh * 56;
        rb[p] = ((b * 58 + oh) * 58 + ow) * 256;
    }
    // B load mapping: 16 rows x 64 cols = 256 float4, 2 per thread
    int bk[2], bc[2];
#pragma unroll
    for (int p = 0; p < 2; p++) {
        int v = tid + 128 * p;
        bk[p] = v >> 4;
        bc[p] = (v & 15) << 2;
    }

    float acc[8][4];
#pragma unroll
    for (int i = 0; i < 8; i++)
#pragma unroll
        for (int j = 0; j < 4; j++) acc[i][j] = 0.f;

    const int kStart = z * 768;

    float4 aR[2], bR[2];
    {
        int kt = kStart;
        int tap = kt >> 8, cf = kt & 255;
        int toff = ((tap / 3) * 58 + (tap % 3)) * 256 + cf + aq;
#pragma unroll
        for (int p = 0; p < 2; p++) aR[p] = *(const float4*)(g_feat + rb[p] + toff);
#pragma unroll
        for (int p = 0; p < 2; p++) bR[p] = *(const float4*)(g_wps + (kt + bk[p]) * 64 + bc[p]);
    }

    for (int s = 0; s < 48; s++) {
        // commit current stage to smem
#pragma unroll
        for (int p = 0; p < 2; p++) {
            int i = aRow + 32 * p;
            As[aq + 0][i] = aR[p].x;
            As[aq + 1][i] = aR[p].y;
            As[aq + 2][i] = aR[p].z;
            As[aq + 3][i] = aR[p].w;
            *(float4*)&Bs[bk[p]][bc[p]] = bR[p];
        }
        __syncthreads();
        // prefetch next stage (global -> regs) while computing
        if (s + 1 < 48) {
            int kt = kStart + (s + 1) * 16;
            int tap = kt >> 8, cf = kt & 255;
            int toff = ((tap / 3) * 58 + (tap % 3)) * 256 + cf + aq;
#pragma unroll
            for (int p = 0; p < 2; p++) aR[p] = *(const float4*)(g_feat + rb[p] + toff);
#pragma unroll
            for (int p = 0; p < 2; p++) bR[p] = *(const float4*)(g_wps + (kt + bk[p]) * 64 + bc[p]);
        }
#pragma unroll
        for (int kk = 0; kk < 16; kk++) {
            float4 a0 = *(const float4*)&As[kk][ty * 8];
            float4 a1 = *(const float4*)&As[kk][ty * 8 + 4];
            float4 b4 = *(const float4*)&Bs[kk][tx * 4];
            float a[8] = {a0.x, a0.y, a0.z, a0.w, a1.x, a1.y, a1.z, a1.w};
            float bv[4] = {b4.x, b4.y, b4.z, b4.w};
#pragma unroll
            for (int i = 0; i < 8; i++)
#pragma unroll
                for (int j = 0; j < 4; j++)
                    acc[i][j] = fmaf(a[i], bv[j], acc[i][j]);
        }
        __syncthreads();
    }

    float* sp = g_S + ((size_t)z * MTOT + mBase) * 64;
#pragma unroll
    for (int i = 0; i < 8; i++) {
        int row = ty * 8 + i;
        float4 v = make_float4(acc[i][0], acc[i][1], acc[i][2], acc[i][3]);
        *(float4*)(sp + (size_t)row * 64 + tx * 4) = v;
    }
}

// ---------------- kernel 5: base-conv GEMM (K=288) + fused epilogue ----------------
// out[b][o][oh][ow] = silu(base) + scaler[o] * (S0+S1+S2)
__global__ void __launch_bounds__(128) base_gemm_kernel(const float* __restrict__ scaler,
                                                        float* __restrict__ out)
{
    __shared__ float As[16][64];
    __shared__ float Bs[16][64];

    const int tid   = threadIdx.x;
    const int mBase = blockIdx.x * 64;
    const int ty = tid >> 4;
    const int tx = tid & 15;
    const int aRow = tid >> 2;
    const int aq   = (tid & 3) << 2;

    int rb[2];
#pragma unroll
    for (int p = 0; p < 2; p++) {
        int r = mBase + aRow + 32 * p;
        int b = r / 3136; int rem = r - b * 3136;
        int oh = rem / 56; int ow = rem - oh * 56;
        rb[p] = ((b * 58 + oh) * 58 + ow) * 32;
    }
    int bk[2], bc[2];
#pragma unroll
    for (int p = 0; p < 2; p++) {
        int v = tid + 128 * p;
        bk[p] = v >> 4;
        bc[p] = (v & 15) << 2;
    }

    float acc[8][4];
#pragma unroll
    for (int i = 0; i < 8; i++)
#pragma unroll
        for (int j = 0; j < 4; j++) acc[i][j] = 0.f;

    float4 aR[2], bR[2];
    {
        int kt = 0;
        int tap = kt >> 5, cf = kt & 31;
        int toff = ((tap / 3) * 58 + (tap % 3)) * 32 + cf + aq;
#pragma unroll
        for (int p = 0; p < 2; p++) aR[p] = *(const float4*)(g_xp + rb[p] + toff);
#pragma unroll
        for (int p = 0; p < 2; p++) bR[p] = *(const float4*)(g_wpb + (kt + bk[p]) * 64 + bc[p]);
    }

    for (int s = 0; s < 18; s++) {
#pragma unroll
        for (int p = 0; p < 2; p++) {
            int i = aRow + 32 * p;
            As[aq + 0][i] = aR[p].x;
            As[aq + 1][i] = aR[p].y;
            As[aq + 2][i] = aR[p].z;
            As[aq + 3][i] = aR[p].w;
            *(float4*)&Bs[bk[p]][bc[p]] = bR[p];
        }
        __syncthreads();
        if (s + 1 < 18) {
            int kt = (s + 1) * 16;
            int tap = kt >> 5, cf = kt & 31;
            int toff = ((tap / 3) * 58 + (tap % 3)) * 32 + cf + aq;
#pragma unroll
            for (int p = 0; p < 2; p++) aR[p] = *(const float4*)(g_xp + rb[p] + toff);
#pragma unroll
            for (int p = 0; p < 2; p++) bR[p] = *(const float4*)(g_wpb + (kt + bk[p]) * 64 + bc[p]);
        }
#pragma unroll
        for (int kk = 0; kk < 16; kk++) {
            float4 a0 = *(const float4*)&As[kk][ty * 8];
            float4 a1 = *(const float4*)&As[kk][ty * 8 + 4];
            float4 b4 = *(const float4*)&Bs[kk][tx * 4];
            float a[8] = {a0.x, a0.y, a0.z, a0.w, a1.x, a1.y, a1.z, a1.w};
            float bv[4] = {b4.x, b4.y, b4.z, b4.w};
#pragma unroll
            for (int i = 0; i < 8; i++)
#pragma unroll
                for (int j = 0; j < 4; j++)
                    acc[i][j] = fmaf(a[i], bv[j], acc[i][j]);
        }
        __syncthreads();
    }

    // fused epilogue
    float4 sc4 = *(const float4*)(scaler + tx * 4);
    float scv[4] = {sc4.x, sc4.y, sc4.z, sc4.w};
#pragma unroll
    for (int i = 0; i < 8; i++) {
        int m = mBase + ty * 8 + i;
        int b = m / 3136; int ssp = m - b * 3136;
        const float* s0 = g_S + (size_t)m * 64 + tx * 4;
        float4 v0 = *(const float4*)(s0);
        float4 v1 = *(const float4*)(s0 + (size_t)MTOT * 64);
        float4 v2 = *(const float4*)(s0 + (size_t)2 * MTOT * 64);
        float sv[4] = {v0.x + v1.x + v2.x, v0.y + v1.y + v2.y,
                       v0.z + v1.z + v2.z, v0.w + v1.w + v2.w};
#pragma unroll
        for (int j = 0; j < 4; j++) {
            float bb = acc[i][j];
            float silu = bb / (1.0f + expf(-bb));
            out[(size_t)(b * 64 + tx * 4 + j) * 3136 + ssp] = silu + scv[j] * sv[j];
        }
    }
}

// ---------------- launch ----------------
extern "C" void kernel_launch(void* const* d_in, const int* in_sizes, int n_in,
                              void* d_out, int out_size)
{
    const float* x  = (const float*)d_in[0];  // (4,32,56,56)
    const float* bw = (const float*)d_in[1];  // (64,32,3,3)
    const float* sw = (const float*)d_in[2];  // (64,288,8)
    const float* sc = (const float*)d_in[3];  // (64,)
    float* out = (float*)d_out;               // (4,64,56,56) f32

    {   // 1. pack weights
        int total = (KSPL + KBAS) * OUTC;
        pack_kernel<<<(total + 255) / 256, 256>>>(sw, bw);
    }
    {   // 2. init padded scratch (g_feat border = bases(0), g_xp border = 0)
        int n4 = (FEAT_SZ + XP_SZ) / 4;
        init_kernel<<<(n4 + 255) / 256, 256>>>();
    }
    {   // 3. per-pixel basis expansion
        int total = BATCH * INC * HW * HW;
        fill_kernel<<<(total + 255) / 256, 256>>>(x);
    }
    {   // 4. spline GEMM (split-K = 3 -> 588 blocks, ~4/SM)
        dim3 grid(MTOT / 64, 1, SPLITK);
        spline_gemm_kernel<<<grid, 128>>>();
    }
    {   // 5. base GEMM + fused silu/scale/add epilogue
        base_gemm_kernel<<<MTOT / 64, 128>>>(sc, out);
    }
}

// round 5
// speedup vs baseline: 1.3227x; 1.3227x over previous
#include <cuda_runtime.h>
#include <cuda_fp16.h>
#include <math.h>
#include <stdint.h>

// ---------------- problem constants ----------------
#define BATCH 4
#define INC   32
#define OUTC  64
#define HW    56
#define PH    58
#define MTOT  (BATCH*HW*HW)              // 12544
#define NPIX  (BATCH*PH*PH)              // 13456 padded pixels
#define KSPL  2304                       // 9 taps * 256
#define KBAS  288                        // 9 taps * 32
#define NCH_S 72                         // spline chunks of k=32
#define NCH_B 9                          // base chunks of k=32
#define NCH   81

// ---------------- scratch (device globals; fp16 hi/lo pre-split) ----------------
__device__ __half g_fh[NPIX*256];        // basis features hi  [pix][c*8+f]
__device__ __half g_fl[NPIX*256];        // basis features lo
__device__ __half g_xph[NPIX*32];        // raw x hi           [pix][c]
__device__ __half g_xpl[NPIX*32];
__device__ __half g_wsh[OUTC*KSPL];      // spline W hi [o][k]
__device__ __half g_wsl[OUTC*KSPL];
__device__ __half g_wbh[OUTC*KBAS];      // base W hi   [o][k]
__device__ __half g_wbl[OUTC*KBAS];

// ---------------- helpers ----------------
__device__ __forceinline__ uint32_t smem_u32(const void* p) {
    uint32_t a;
    asm("{ .reg .u64 t; cvta.to.shared.u64 t, %1; cvt.u32.u64 %0, t; }" : "=r"(a) : "l"(p));
    return a;
}
#define CPA16(sm, gp) asm volatile("cp.async.cg.shared.global [%0], [%1], 16;" :: "r"(sm), "l"(gp))
#define CP_COMMIT()   asm volatile("cp.async.commit_group;" ::: "memory")
#define CP_WAIT1()    asm volatile("cp.async.wait_group 1;" ::: "memory")
#define CP_WAIT0()    asm volatile("cp.async.wait_group 0;" ::: "memory")

__device__ __forceinline__ void mma16816(float* d, const uint32_t* a, const uint32_t* b) {
    asm volatile(
        "mma.sync.aligned.m16n8k16.row.col.f32.f16.f16.f32 "
        "{%0,%1,%2,%3}, {%4,%5,%6,%7}, {%8,%9}, {%0,%1,%2,%3};"
        : "+f"(d[0]), "+f"(d[1]), "+f"(d[2]), "+f"(d[3])
        : "r"(a[0]), "r"(a[1]), "r"(a[2]), "r"(a[3]), "r"(b[0]), "r"(b[1]));
}

// ---------------- knots / bspline (matches reference; recips are exact-uniform) ----------------
__device__ __forceinline__ float knot(int i) { return (float)(i - 3) * 0.4f - 1.0f; }

__device__ __forceinline__ void bspline8(float xv, float* out8) {
    float bb[11];
#pragma unroll
    for (int i = 0; i < 11; i++)
        bb[i] = (xv >= knot(i) && xv < knot(i + 1)) ? 1.0f : 0.0f;
    const float RK1 = 2.5f, RK2 = 1.25f, RK3 = 1.0f / 1.2f;
#pragma unroll
    for (int i = 0; i < 10; i++)
        bb[i] = (xv - knot(i)) * RK1 * bb[i] + (knot(i + 2) - xv) * RK1 * bb[i + 1];
#pragma unroll
    for (int i = 0; i < 9; i++)
        bb[i] = (xv - knot(i)) * RK2 * bb[i] + (knot(i + 3) - xv) * RK2 * bb[i + 1];
#pragma unroll
    for (int i = 0; i < 8; i++)
        bb[i] = (xv - knot(i)) * RK3 * bb[i] + (knot(i + 4) - xv) * RK3 * bb[i + 1];
#pragma unroll
    for (int i = 0; i < 8; i++) out8[i] = bb[i];
}

// ---------------- kernel 1: pack weights to fp16 hi/lo, [o][k] ----------------
__global__ void pack_kernel(const float* __restrict__ sw, const float* __restrict__ bw)
{
    int t = blockIdx.x * blockDim.x + threadIdx.x;
    const int NS = OUTC * KSPL;
    const int NB = OUTC * KBAS;
    if (t < NS) {
        int o = t / KSPL;
        int k = t - o * KSPL;           // k = tap*256 + c*8 + f
        int tap = k >> 8, cf = k & 255;
        int c = cf >> 3, f = cf & 7;
        float v = sw[(o * 288 + c * 9 + tap) * 8 + f];
        __half h = __float2half_rn(v);
        g_wsh[t] = h;
        g_wsl[t] = __float2half_rn(v - __half2float(h));
    } else if (t < NS + NB) {
        int u = t - NS;
        int o = u / KBAS;
        int k = u - o * KBAS;           // k = tap*32 + c
        int tap = k >> 5, c = k & 31;
        float v = bw[(o * 32 + c) * 9 + tap];
        __half h = __float2half_rn(v);
        g_wbh[u] = h;
        g_wbl[u] = __float2half_rn(v - __half2float(h));
    }
}

// ---------------- kernel 2: basis fill over the PADDED grid ----------------
// Reference applies B-spline bases to padded zeros too (bases(0) != 0), so the
// border gets bspline8(0) via the same code path; xp border is true zero.
__global__ void fillpad_kernel(const float* __restrict__ x)
{
    int t = blockIdx.x * blockDim.x + threadIdx.x;
    if (t >= NPIX * 32) return;
    int c = t & 31;
    int pix = t >> 5;
    int w = pix % 58;
    int tmp = pix / 58;
    int h = tmp % 58;
    int b = tmp / 58;

    float xv = 0.0f;
    if (h >= 1 && h <= 56 && w >= 1 && w <= 56)
        xv = x[((b * 32 + c) * 56 + (h - 1)) * 56 + (w - 1)];

    float bb[8];
    bspline8(xv, bb);

    __half2 hh[4], hl[4];
#pragma unroll
    for (int i = 0; i < 4; i++) {
        __half h0 = __float2half_rn(bb[2 * i]);
        __half h1 = __float2half_rn(bb[2 * i + 1]);
        hh[i] = __halves2half2(h0, h1);
        hl[i] = __halves2half2(__float2half_rn(bb[2 * i] - __half2float(h0)),
                               __float2half_rn(bb[2 * i + 1] - __half2float(h1)));
    }
    size_t fo = (size_t)pix * 256 + c * 8;
    *(uint4*)(g_fh + fo) = *(uint4*)hh;
    *(uint4*)(g_fl + fo) = *(uint4*)hl;

    __half xh = __float2half_rn(xv);
    g_xph[pix * 32 + c] = xh;
    g_xpl[pix * 32 + c] = __float2half_rn(xv - __half2float(xh));
}

// ---------------- kernel 3: fused mma.sync GEMM (spline K=2304 + base K=288) ----------------
// Block: 128 threads (4 warps as 2Mx2N), tile M=64 N=64, BK=32, double-buffered
// cp.async staging. 3-pass fp16 error-compensated MMA: Ah*Bh + Al*Bh + Ah*Bl.
#define ASTRIDE 40   // halfs per smem row (80B, conflict-free frag loads)

__global__ void __launch_bounds__(128) kan_mma_kernel(const float* __restrict__ scaler,
                                                      float* __restrict__ out)
{
    __shared__ __align__(16) __half sAh[2][64 * ASTRIDE];
    __shared__ __align__(16) __half sAl[2][64 * ASTRIDE];
    __shared__ __align__(16) __half sBh[2][64 * ASTRIDE];
    __shared__ __align__(16) __half sBl[2][64 * ASTRIDE];

    const int tid  = threadIdx.x;
    const int wid  = tid >> 5, lane = tid & 31;
    const int wm   = wid >> 1, wn = wid & 1;          // 2x2 warp grid
    const int g    = lane >> 2, tg = lane & 3;
    const int mBase = blockIdx.x * 64;

    // loader role: thread handles one A row + one B row, two 16B segs
    const int lrow = tid >> 1;
    const int lsg0 = (tid & 1) * 2;
    int lm = mBase + lrow;
    int lb = lm / 3136; int lrem = lm - lb * 3136;
    int loh = lrem / 56, low = lrem - loh * 56;
    const int ppix = (lb * 58 + loh) * 58 + low;      // top-left padded pixel of patch

    // smem byte offset for this thread's two segments
    const uint32_t so0 = (uint32_t)(lrow * ASTRIDE + lsg0 * 8) * 2;

    float accS[2][4][4] = {};
    float accB[2][4][4] = {};

    auto load_stage = [&](int ch, int st) {
        const __half *ga_h, *ga_l, *gb_h, *gb_l;
        if (ch < NCH_S) {
            int tap = ch >> 3;
            int cf0 = (ch & 7) * 32;
            int toff = ((tap / 3) * 58 + (tap % 3)) * 256 + cf0;
            ga_h = g_fh + (size_t)ppix * 256 + toff;
            ga_l = g_fl + (size_t)ppix * 256 + toff;
            int kt = ch * 32;
            gb_h = g_wsh + lrow * KSPL + kt;
            gb_l = g_wsl + lrow * KSPL + kt;
        } else {
            int tap = ch - NCH_S;
            int toff = ((tap / 3) * 58 + (tap % 3)) * 32;
            ga_h = g_xph + (size_t)ppix * 32 + toff;
            ga_l = g_xpl + (size_t)ppix * 32 + toff;
            int kt = tap * 32;
            gb_h = g_wbh + lrow * KBAS + kt;
            gb_l = g_wbl + lrow * KBAS + kt;
        }
        uint32_t ah = smem_u32(&sAh[st][0]) + so0;
        uint32_t al = smem_u32(&sAl[st][0]) + so0;
        uint32_t bh = smem_u32(&sBh[st][0]) + so0;
        uint32_t bl = smem_u32(&sBl[st][0]) + so0;
#pragma unroll
        for (int s = 0; s < 2; s++) {
            int e = (lsg0 + s) * 8;          // half offset within row
            CPA16(ah + s * 16, ga_h + e);
            CPA16(al + s * 16, ga_l + e);
            CPA16(bh + s * 16, gb_h + e);
            CPA16(bl + s * 16, gb_l + e);
        }
    };

    auto do_chunk = [&](float (&acc)[2][4][4], int st) {
        const __half* Ah = sAh[st];
        const __half* Al = sAl[st];
        const __half* Bh = sBh[st];
        const __half* Bl = sBl[st];
#pragma unroll
        for (int k0 = 0; k0 < 32; k0 += 16) {
            uint32_t ah[2][4], al[2][4], bh[4][2], bl[4][2];
            const int cb = k0 + 2 * tg;
#pragma unroll
            for (int mi = 0; mi < 2; mi++) {
                int r = wm * 32 + mi * 16 + g;
                ah[mi][0] = *(const uint32_t*)&Ah[r * ASTRIDE + cb];
                ah[mi][1] = *(const uint32_t*)&Ah[(r + 8) * ASTRIDE + cb];
                ah[mi][2] = *(const uint32_t*)&Ah[r * ASTRIDE + cb + 8];
                ah[mi][3] = *(const uint32_t*)&Ah[(r + 8) * ASTRIDE + cb + 8];
                al[mi][0] = *(const uint32_t*)&Al[r * ASTRIDE + cb];
                al[mi][1] = *(const uint32_t*)&Al[(r + 8) * ASTRIDE + cb];
                al[mi][2] = *(const uint32_t*)&Al[r * ASTRIDE + cb + 8];
                al[mi][3] = *(const uint32_t*)&Al[(r + 8) * ASTRIDE + cb + 8];
            }
#pragma unroll
            for (int nj = 0; nj < 4; nj++) {
                int n = wn * 32 + nj * 8 + g;
                bh[nj][0] = *(const uint32_t*)&Bh[n * ASTRIDE + cb];
                bh[nj][1] = *(const uint32_t*)&Bh[n * ASTRIDE + cb + 8];
                bl[nj][0] = *(const uint32_t*)&Bl[n * ASTRIDE + cb];
                bl[nj][1] = *(const uint32_t*)&Bl[n * ASTRIDE + cb + 8];
            }
#pragma unroll
            for (int mi = 0; mi < 2; mi++)
#pragma unroll
                for (int nj = 0; nj < 4; nj++) {
                    mma16816(acc[mi][nj], ah[mi], bh[nj]);
                    mma16816(acc[mi][nj], al[mi], bh[nj]);
                    mma16816(acc[mi][nj], ah[mi], bl[nj]);
                }
        }
    };

    load_stage(0, 0);
    CP_COMMIT();
    for (int ch = 0; ch < NCH; ch++) {
        int st = ch & 1;
        if (ch + 1 < NCH) {
            load_stage(ch + 1, st ^ 1);
            CP_COMMIT();
            CP_WAIT1();
        } else {
            CP_WAIT0();
        }
        __syncthreads();
        if (ch < NCH_S) do_chunk(accS, st);
        else            do_chunk(accB, st);
        __syncthreads();
    }

    // ---- epilogue: silu(base) + scaler*spline ----
    float scl[4][2];
#pragma unroll
    for (int nj = 0; nj < 4; nj++) {
        int o0 = wn * 32 + nj * 8 + 2 * tg;
        scl[nj][0] = scaler[o0];
        scl[nj][1] = scaler[o0 + 1];
    }
#pragma unroll
    for (int mi = 0; mi < 2; mi++) {
#pragma unroll
        for (int gg = 0; gg < 2; gg++) {
            int row = wm * 32 + mi * 16 + g + gg * 8;
            int m = mBase + row;
            int b = m / 3136; int ssp = m - b * 3136;
            float* ob = out + (size_t)b * 64 * 3136 + ssp;
#pragma unroll
            for (int nj = 0; nj < 4; nj++) {
                int o0 = wn * 32 + nj * 8 + 2 * tg;
#pragma unroll
                for (int cc = 0; cc < 2; cc++) {
                    float bv = accB[mi][nj][gg * 2 + cc];
                    float sv = accS[mi][nj][gg * 2 + cc];
                    float silu = bv / (1.0f + __expf(-bv));
                    ob[(size_t)(o0 + cc) * 3136] = silu + scl[nj][cc] * sv;
                }
            }
        }
    }
}

// ---------------- launch ----------------
extern "C" void kernel_launch(void* const* d_in, const int* in_sizes, int n_in,
                              void* d_out, int out_size)
{
    const float* x  = (const float*)d_in[0];  // (4,32,56,56)
    const float* bw = (const float*)d_in[1];  // (64,32,3,3)
    const float* sw = (const float*)d_in[2];  // (64,288,8)
    const float* sc = (const float*)d_in[3];  // (64,)
    float* out = (float*)d_out;               // (4,64,56,56)

    {   // 1. pack weights (fp16 hi/lo, [o][k])
        int total = OUTC * (KSPL + KBAS);
        pack_kernel<<<(total + 255) / 256, 256>>>(sw, bw);
    }
    {   // 2. basis expansion over the padded grid (border = bases(0))
        int total = NPIX * 32;
        fillpad_kernel<<<(total + 255) / 256, 256>>>(x);
    }
    {   // 3. fused spline+base GEMM + epilogue (196 blocks)
        kan_mma_kernel<<<MTOT / 64, 128>>>(sc, out);
    }
}

// round 7
// speedup vs baseline: 1.5965x; 1.2070x over previous
#include <cuda_runtime.h>
#include <cuda_fp16.h>
#include <math.h>
#include <stdint.h>

// ---------------- problem constants ----------------
#define BATCH 4
#define INC   32
#define OUTC  64
#define HW    56
#define PH    58
#define MTOT  (BATCH*HW*HW)              // 12544
#define NPIX  (BATCH*PH*PH)              // 13456 padded pixels
#define KSPL  2304                       // 9 taps * 256
#define KBAS  288                        // 9 taps * 32
#define NCH_S 72                         // spline chunks of k=32
#define NCH   81                         // + 9 base chunks
#define CPB   27                         // chunks per block (81/3)

// ---------------- scratch (device globals; fp16 hi/lo pre-split) ----------------
__device__ __half g_fh[NPIX*256];        // basis features hi  [pix][c*8+f]
__device__ __half g_fl[NPIX*256];        // basis features lo
__device__ __half g_xph[NPIX*32];        // raw x hi           [pix][c]
__device__ __half g_xpl[NPIX*32];
__device__ __half g_wsh[OUTC*KSPL];      // spline W hi [o][k]
__device__ __half g_wsl[OUTC*KSPL];
__device__ __half g_wbh[OUTC*KBAS];      // base W hi   [o][k]
__device__ __half g_wbl[OUTC*KBAS];
__device__ float  g_S[3*MTOT*OUTC];      // spline split-K partials [z][m][o]
__device__ float  g_Bc[MTOT*OUTC];       // base conv result        [m][o]

// ---------------- helpers ----------------
__device__ __forceinline__ uint32_t smem_u32(const void* p) {
    uint32_t a;
    asm("{ .reg .u64 t; cvta.to.shared.u64 t, %1; cvt.u32.u64 %0, t; }" : "=r"(a) : "l"(p));
    return a;
}
#define CPA16(sm, gp) asm volatile("cp.async.cg.shared.global [%0], [%1], 16;" :: "r"(sm), "l"(gp))
#define CP_COMMIT()   asm volatile("cp.async.commit_group;" ::: "memory")
#define CP_WAIT1()    asm volatile("cp.async.wait_group 1;" ::: "memory")
#define CP_WAIT0()    asm volatile("cp.async.wait_group 0;" ::: "memory")

__device__ __forceinline__ void mma16816(float* d, const uint32_t* a, const uint32_t* b) {
    asm volatile(
        "mma.sync.aligned.m16n8k16.row.col.f32.f16.f16.f32 "
        "{%0,%1,%2,%3}, {%4,%5,%6,%7}, {%8,%9}, {%0,%1,%2,%3};"
        : "+f"(d[0]), "+f"(d[1]), "+f"(d[2]), "+f"(d[3])
        : "r"(a[0]), "r"(a[1]), "r"(a[2]), "r"(a[3]), "r"(b[0]), "r"(b[1]));
}

// ---------------- knots / bspline ----------------
__device__ __forceinline__ float knot(int i) { return (float)(i - 3) * 0.4f - 1.0f; }

__device__ __forceinline__ void bspline8(float xv, float* out8) {
    float bb[11];
#pragma unroll
    for (int i = 0; i < 11; i++)
        bb[i] = (xv >= knot(i) && xv < knot(i + 1)) ? 1.0f : 0.0f;
    const float RK1 = 2.5f, RK2 = 1.25f, RK3 = 1.0f / 1.2f;
#pragma unroll
    for (int i = 0; i < 10; i++)
        bb[i] = (xv - knot(i)) * RK1 * bb[i] + (knot(i + 2) - xv) * RK1 * bb[i + 1];
#pragma unroll
    for (int i = 0; i < 9; i++)
        bb[i] = (xv - knot(i)) * RK2 * bb[i] + (knot(i + 3) - xv) * RK2 * bb[i + 1];
#pragma unroll
    for (int i = 0; i < 8; i++)
        bb[i] = (xv - knot(i)) * RK3 * bb[i] + (knot(i + 4) - xv) * RK3 * bb[i + 1];
#pragma unroll
    for (int i = 0; i < 8; i++) out8[i] = bb[i];
}

// ---------------- kernel 1: pack weights to fp16 hi/lo, [o][k] ----------------
__global__ void pack_kernel(const float* __restrict__ sw, const float* __restrict__ bw)
{
    int t = blockIdx.x * blockDim.x + threadIdx.x;
    const int NS = OUTC * KSPL;
    const int NB = OUTC * KBAS;
    if (t < NS) {
        int o = t / KSPL;
        int k = t - o * KSPL;           // k = tap*256 + c*8 + f
        int tap = k >> 8, cf = k & 255;
        int c = cf >> 3, f = cf & 7;
        float v = sw[(o * 288 + c * 9 + tap) * 8 + f];
        __half h = __float2half_rn(v);
        g_wsh[t] = h;
        g_wsl[t] = __float2half_rn(v - __half2float(h));
    } else if (t < NS + NB) {
        int u = t - NS;
        int o = u / KBAS;
        int k = u - o * KBAS;           // k = tap*32 + c
        int tap = k >> 5, c = k & 31;
        float v = bw[(o * 32 + c) * 9 + tap];
        __half h = __float2half_rn(v);
        g_wbh[u] = h;
        g_wbl[u] = __float2half_rn(v - __half2float(h));
    }
}

// ---------------- kernel 2: basis fill over the PADDED grid ----------------
// Reference applies B-spline bases to padded zeros too (bases(0) != 0).
__global__ void fillpad_kernel(const float* __restrict__ x)
{
    int t = blockIdx.x * blockDim.x + threadIdx.x;
    if (t >= NPIX * 32) return;
    int c = t & 31;
    int pix = t >> 5;
    int w = pix % 58;
    int tmp = pix / 58;
    int h = tmp % 58;
    int b = tmp / 58;

    float xv = 0.0f;
    if (h >= 1 && h <= 56 && w >= 1 && w <= 56)
        xv = x[((b * 32 + c) * 56 + (h - 1)) * 56 + (w - 1)];

    float bb[8];
    bspline8(xv, bb);

    __half2 hh[4], hl[4];
#pragma unroll
    for (int i = 0; i < 4; i++) {
        __half h0 = __float2half_rn(bb[2 * i]);
        __half h1 = __float2half_rn(bb[2 * i + 1]);
        hh[i] = __halves2half2(h0, h1);
        hl[i] = __halves2half2(__float2half_rn(bb[2 * i] - __half2float(h0)),
                               __float2half_rn(bb[2 * i + 1] - __half2float(h1)));
    }
    size_t fo = (size_t)pix * 256 + c * 8;
    *(uint4*)(g_fh + fo) = *(uint4*)hh;
    *(uint4*)(g_fl + fo) = *(uint4*)hl;

    __half xh = __float2half_rn(xv);
    g_xph[pix * 32 + c] = xh;
    g_xpl[pix * 32 + c] = __float2half_rn(xv - __half2float(xh));
}

// ---------------- kernel 3: split-K mma.sync GEMM ----------------
// grid (196, 3): 588 uniform blocks, each does exactly 27 k=32 chunks.
// z=0: spline chunks 0-26; z=1: 27-53; z=2: spline 54-71 + base 0-8.
// Tile M=64 N=64, 128 threads (2x2 warps), double-buffered cp.async.
// 3-pass fp16 error compensation: Ah*Bh + Al*Bh + Ah*Bl (fp32 acc).
#define ASTRIDE 40   // halfs per smem row (80B, conflict-free)

__global__ void __launch_bounds__(128) kan_mma_kernel()
{
    __shared__ __align__(16) __half sAh[2][64 * ASTRIDE];
    __shared__ __align__(16) __half sAl[2][64 * ASTRIDE];
    __shared__ __align__(16) __half sBh[2][64 * ASTRIDE];
    __shared__ __align__(16) __half sBl[2][64 * ASTRIDE];

    const int tid  = threadIdx.x;
    const int wid  = tid >> 5, lane = tid & 31;
    const int wm   = wid >> 1, wn = wid & 1;
    const int g    = lane >> 2, tg = lane & 3;
    const int mBase = blockIdx.x * 64;
    const int z     = blockIdx.y;
    const int chBase = z * CPB;

    const int lrow = tid >> 1;
    const int lsg0 = (tid & 1) * 2;
    int lm = mBase + lrow;
    int lb = lm / 3136; int lrem = lm - lb * 3136;
    int loh = lrem / 56, low = lrem - loh * 56;
    const int ppix = (lb * 58 + loh) * 58 + low;

    const uint32_t so0 = (uint32_t)(lrow * ASTRIDE + lsg0 * 8) * 2;

    float accS[2][4][4] = {};
    float accB[2][4][4] = {};

    auto load_stage = [&](int ch, int st) {
        const __half *ga_h, *ga_l, *gb_h, *gb_l;
        if (ch < NCH_S) {
            int tap = ch >> 3;
            int cf0 = (ch & 7) * 32;
            int toff = ((tap / 3) * 58 + (tap % 3)) * 256 + cf0;
            ga_h = g_fh + (size_t)ppix * 256 + toff;
            ga_l = g_fl + (size_t)ppix * 256 + toff;
            int kt = ch * 32;
            gb_h = g_wsh + lrow * KSPL + kt;
            gb_l = g_wsl + lrow * KSPL + kt;
        } else {
            int tap = ch - NCH_S;
            int toff = ((tap / 3) * 58 + (tap % 3)) * 32;
            ga_h = g_xph + (size_t)ppix * 32 + toff;
            ga_l = g_xpl + (size_t)ppix * 32 + toff;
            int kt = tap * 32;
            gb_h = g_wbh + lrow * KBAS + kt;
            gb_l = g_wbl + lrow * KBAS + kt;
        }
        uint32_t ah = smem_u32(&sAh[st][0]) + so0;
        uint32_t al = smem_u32(&sAl[st][0]) + so0;
        uint32_t bh = smem_u32(&sBh[st][0]) + so0;
        uint32_t bl = smem_u32(&sBl[st][0]) + so0;
#pragma unroll
        for (int s = 0; s < 2; s++) {
            int e = (lsg0 + s) * 8;
            CPA16(ah + s * 16, ga_h + e);
            CPA16(al + s * 16, ga_l + e);
            CPA16(bh + s * 16, gb_h + e);
            CPA16(bl + s * 16, gb_l + e);
        }
    };

    auto do_chunk = [&](float (&acc)[2][4][4], int st) {
        const __half* Ah = sAh[st];
        const __half* Al = sAl[st];
        const __half* Bh = sBh[st];
        const __half* Bl = sBl[st];
#pragma unroll
        for (int k0 = 0; k0 < 32; k0 += 16) {
            uint32_t ah[2][4], al[2][4], bh[4][2], bl[4][2];
            const int cb = k0 + 2 * tg;
#pragma unroll
            for (int mi = 0; mi < 2; mi++) {
                int r = wm * 32 + mi * 16 + g;
                ah[mi][0] = *(const uint32_t*)&Ah[r * ASTRIDE + cb];
                ah[mi][1] = *(const uint32_t*)&Ah[(r + 8) * ASTRIDE + cb];
                ah[mi][2] = *(const uint32_t*)&Ah[r * ASTRIDE + cb + 8];
                ah[mi][3] = *(const uint32_t*)&Ah[(r + 8) * ASTRIDE + cb + 8];
                al[mi][0] = *(const uint32_t*)&Al[r * ASTRIDE + cb];
                al[mi][1] = *(const uint32_t*)&Al[(r + 8) * ASTRIDE + cb];
                al[mi][2] = *(const uint32_t*)&Al[r * ASTRIDE + cb + 8];
                al[mi][3] = *(const uint32_t*)&Al[(r + 8) * ASTRIDE + cb + 8];
            }
#pragma unroll
            for (int nj = 0; nj < 4; nj++) {
                int n = wn * 32 + nj * 8 + g;
                bh[nj][0] = *(const uint32_t*)&Bh[n * ASTRIDE + cb];
                bh[nj][1] = *(const uint32_t*)&Bh[n * ASTRIDE + cb + 8];
                bl[nj][0] = *(const uint32_t*)&Bl[n * ASTRIDE + cb];
                bl[nj][1] = *(const uint32_t*)&Bl[n * ASTRIDE + cb + 8];
            }
#pragma unroll
            for (int mi = 0; mi < 2; mi++)
#pragma unroll
                for (int nj = 0; nj < 4; nj++) {
                    mma16816(acc[mi][nj], ah[mi], bh[nj]);
                    mma16816(acc[mi][nj], al[mi], bh[nj]);
                    mma16816(acc[mi][nj], ah[mi], bl[nj]);
                }
        }
    };

    load_stage(chBase, 0);
    CP_COMMIT();
    for (int i = 0; i < CPB; i++) {
        int ch = chBase + i;
        int st = i & 1;
        if (i + 1 < CPB) {
            load_stage(ch + 1, st ^ 1);
            CP_COMMIT();
            CP_WAIT1();
        } else {
            CP_WAIT0();
        }
        __syncthreads();
        if (ch < NCH_S) do_chunk(accS, st);
        else            do_chunk(accB, st);
        __syncthreads();
    }

    // ---- store partials [m][o]; z==2 also stores base result ----
    float* Sp = g_S + (size_t)z * MTOT * 64;
#pragma unroll
    for (int mi = 0; mi < 2; mi++) {
#pragma unroll
        for (int gg = 0; gg < 2; gg++) {
            int row = wm * 32 + mi * 16 + g + gg * 8;
            size_t m = mBase + row;
#pragma unroll
            for (int nj = 0; nj < 4; nj++) {
                int o0 = wn * 32 + nj * 8 + 2 * tg;
                *(float2*)&Sp[m * 64 + o0] =
                    make_float2(accS[mi][nj][gg * 2], accS[mi][nj][gg * 2 + 1]);
                if (z == 2)
                    *(float2*)&g_Bc[m * 64 + o0] =
                        make_float2(accB[mi][nj][gg * 2], accB[mi][nj][gg * 2 + 1]);
            }
        }
    }
}

// ---------------- kernel 4: reduce + silu + scaler epilogue ----------------
__global__ void reduce_kernel(const float* __restrict__ scaler, float* __restrict__ out)
{
    int t = blockIdx.x * blockDim.x + threadIdx.x;
    const int M4 = MTOT / 4;                   // 3136
    if (t >= OUTC * M4) return;
    int m4 = t % M4;
    int o  = t / M4;
    int m0 = m4 * 4;
    float sc = scaler[o];
    float res[4];
#pragma unroll
    for (int i = 0; i < 4; i++) {
        size_t m = m0 + i;
        float s = g_S[m * 64 + o]
                + g_S[((size_t)MTOT + m) * 64 + o]
                + g_S[((size_t)2 * MTOT + m) * 64 + o];
        float bv = g_Bc[m * 64 + o];
        float silu = bv / (1.0f + expf(-bv));
        res[i] = silu + sc * s;
    }
    int b = m0 / 3136; int ssp = m0 - b * 3136;   // all 4 within same image
    *(float4*)(out + ((size_t)(b * 64 + o)) * 3136 + ssp) =
        make_float4(res[0], res[1], res[2], res[3]);
}

// ---------------- launch ----------------
extern "C" void kernel_launch(void* const* d_in, const int* in_sizes, int n_in,
                              void* d_out, int out_size)
{
    const float* x  = (const float*)d_in[0];  // (4,32,56,56)
    const float* bw = (const float*)d_in[1];  // (64,32,3,3)
    const float* sw = (const float*)d_in[2];  // (64,288,8)
    const float* sc = (const float*)d_in[3];  // (64,)
    float* out = (float*)d_out;               // (4,64,56,56)

    {   // 1. pack weights (fp16 hi/lo, [o][k])
        int total = OUTC * (KSPL + KBAS);
        pack_kernel<<<(total + 255) / 256, 256>>>(sw, bw);
    }
    {   // 2. basis expansion over the padded grid
        int total = NPIX * 32;
        fillpad_kernel<<<(total + 255) / 256, 256>>>(x);
    }
    {   // 3. split-K GEMM: 588 uniform blocks (~3.97/SM)
        dim3 grid(MTOT / 64, 3);
        kan_mma_kernel<<<grid, 128>>>();
    }
    {   // 4. reduce + silu + scaler + store
        int total = OUTC * (MTOT / 4);
        reduce_kernel<<<(total + 255) / 256, 256>>>(sc, out);
    }
}

// round 8
// speedup vs baseline: 2.3413x; 1.4665x over previous
#include <cuda_runtime.h>
#include <cuda_fp16.h>
#include <math.h>
#include <stdint.h>

// ---------------- problem constants ----------------
#define BATCH 4
#define INC   32
#define OUTC  64
#define HW    56
#define PH    58
#define MTOT  (BATCH*HW*HW)              // 12544
#define NPIX  (BATCH*PH*PH)              // 13456 padded pixels
#define KSPL  2304                       // 9 taps * 256
#define KBAS  288                        // 9 taps * 32
#define NCH_S 72                         // spline chunks of k=32
#define NCH   81                         // + 9 base chunks
#define CPB   27                         // chunks per block (81/3)

// ---------------- scratch ----------------
// A side: fp16 rounded (single version). B side: fp16 hi/lo exact split.
__device__ __half g_fh[NPIX*256];        // basis features fp16 [pix][c*8+f]
__device__ __half g_xph[NPIX*32];        // raw x fp16          [pix][c]
__device__ __half g_wsh[OUTC*KSPL];      // spline W hi [o][k]
__device__ __half g_wsl[OUTC*KSPL];     // spline W lo
__device__ __half g_wbh[OUTC*KBAS];      // base W hi   [o][k]
__device__ __half g_wbl[OUTC*KBAS];
__device__ float  g_S[3*MTOT*OUTC];      // spline split-K partials [z][m][o]
__device__ float  g_Bc[MTOT*OUTC];       // base conv result        [m][o]

// ---------------- helpers ----------------
__device__ __forceinline__ uint32_t smem_u32(const void* p) {
    uint32_t a;
    asm("{ .reg .u64 t; cvta.to.shared.u64 t, %1; cvt.u32.u64 %0, t; }" : "=r"(a) : "l"(p));
    return a;
}
#define CPA16(sm, gp) asm volatile("cp.async.cg.shared.global [%0], [%1], 16;" :: "r"(sm), "l"(gp))
#define CP_COMMIT()   asm volatile("cp.async.commit_group;" ::: "memory")
#define CP_WAIT1()    asm volatile("cp.async.wait_group 1;" ::: "memory")
#define CP_WAIT0()    asm volatile("cp.async.wait_group 0;" ::: "memory")

__device__ __forceinline__ void mma16816(float* d, const uint32_t* a, const uint32_t* b) {
    asm volatile(
        "mma.sync.aligned.m16n8k16.row.col.f32.f16.f16.f32 "
        "{%0,%1,%2,%3}, {%4,%5,%6,%7}, {%8,%9}, {%0,%1,%2,%3};"
        : "+f"(d[0]), "+f"(d[1]), "+f"(d[2]), "+f"(d[3])
        : "r"(a[0]), "r"(a[1]), "r"(a[2]), "r"(a[3]), "r"(b[0]), "r"(b[1]));
}

// ---------------- knots / bspline ----------------
__device__ __forceinline__ float knot(int i) { return (float)(i - 3) * 0.4f - 1.0f; }

__device__ __forceinline__ void bspline8(float xv, float* out8) {
    float bb[11];
#pragma unroll
    for (int i = 0; i < 11; i++)
        bb[i] = (xv >= knot(i) && xv < knot(i + 1)) ? 1.0f : 0.0f;
    const float RK1 = 2.5f, RK2 = 1.25f, RK3 = 1.0f / 1.2f;
#pragma unroll
    for (int i = 0; i < 10; i++)
        bb[i] = (xv - knot(i)) * RK1 * bb[i] + (knot(i + 2) - xv) * RK1 * bb[i + 1];
#pragma unroll
    for (int i = 0; i < 9; i++)
        bb[i] = (xv - knot(i)) * RK2 * bb[i] + (knot(i + 3) - xv) * RK2 * bb[i + 1];
#pragma unroll
    for (int i = 0; i < 8; i++)
        bb[i] = (xv - knot(i)) * RK3 * bb[i] + (knot(i + 4) - xv) * RK3 * bb[i + 1];
#pragma unroll
    for (int i = 0; i < 8; i++) out8[i] = bb[i];
}

// ---------------- kernel 1: pack weights to fp16 hi/lo, [o][k] ----------------
__global__ void pack_kernel(const float* __restrict__ sw, const float* __restrict__ bw)
{
    int t = blockIdx.x * blockDim.x + threadIdx.x;
    const int NS = OUTC * KSPL;
    const int NB = OUTC * KBAS;
    if (t < NS) {
        int o = t / KSPL;
        int k = t - o * KSPL;           // k = tap*256 + c*8 + f
        int tap = k >> 8, cf = k & 255;
        int c = cf >> 3, f = cf & 7;
        float v = sw[(o * 288 + c * 9 + tap) * 8 + f];
        __half h = __float2half_rn(v);
        g_wsh[t] = h;
        g_wsl[t] = __float2half_rn(v - __half2float(h));
    } else if (t < NS + NB) {
        int u = t - NS;
        int o = u / KBAS;
        int k = u - o * KBAS;           // k = tap*32 + c
        int tap = k >> 5, c = k & 31;
        float v = bw[(o * 32 + c) * 9 + tap];
        __half h = __float2half_rn(v);
        g_wbh[u] = h;
        g_wbl[u] = __float2half_rn(v - __half2float(h));
    }
}

// ---------------- kernel 2: basis fill over the PADDED grid ----------------
// Reference applies B-spline bases to padded zeros too (bases(0) != 0).
__global__ void fillpad_kernel(const float* __restrict__ x)
{
    int t = blockIdx.x * blockDim.x + threadIdx.x;
    if (t >= NPIX * 32) return;
    int c = t & 31;
    int pix = t >> 5;
    int w = pix % 58;
    int tmp = pix / 58;
    int h = tmp % 58;
    int b = tmp / 58;

    float xv = 0.0f;
    if (h >= 1 && h <= 56 && w >= 1 && w <= 56)
        xv = x[((b * 32 + c) * 56 + (h - 1)) * 56 + (w - 1)];

    float bb[8];
    bspline8(xv, bb);

    __half2 hh[4];
#pragma unroll
    for (int i = 0; i < 4; i++)
        hh[i] = __halves2half2(__float2half_rn(bb[2 * i]), __float2half_rn(bb[2 * i + 1]));
    *(uint4*)(g_fh + (size_t)pix * 256 + c * 8) = *(uint4*)hh;
    g_xph[pix * 32 + c] = __float2half_rn(xv);
}

// ---------------- kernel 3: split-K mma.sync GEMM, 2-pass compensation ----------------
// grid (196, 3): 588 uniform blocks, each does exactly 27 k=32 chunks.
// z=0: spline chunks 0-26; z=1: 27-53; z=2: spline 54-71 + base 0-8.
// Tile M=64 N=64, 128 threads (2x2 warps), double-buffered cp.async.
// Passes: rn16(A)*Bh + rn16(A)*Bl  (B split exact; A rounding error ~1.4e-4 global).
#define ASTRIDE 40   // halfs per smem row (80B, conflict-free)

__global__ void __launch_bounds__(128) kan_mma_kernel()
{
    __shared__ __align__(16) __half sA [2][64 * ASTRIDE];
    __shared__ __align__(16) __half sBh[2][64 * ASTRIDE];
    __shared__ __align__(16) __half sBl[2][64 * ASTRIDE];

    const int tid  = threadIdx.x;
    const int wid  = tid >> 5, lane = tid & 31;
    const int wm   = wid >> 1, wn = wid & 1;
    const int g    = lane >> 2, tg = lane & 3;
    const int mBase = blockIdx.x * 64;
    const int z     = blockIdx.y;
    const int chBase = z * CPB;

    const int lrow = tid >> 1;
    const int lsg0 = (tid & 1) * 2;
    int lm = mBase + lrow;
    int lb = lm / 3136; int lrem = lm - lb * 3136;
    int loh = lrem / 56, low = lrem - loh * 56;
    const int ppix = (lb * 58 + loh) * 58 + low;

    const uint32_t so0 = (uint32_t)(lrow * ASTRIDE + lsg0 * 8) * 2;

    float accS[2][4][4] = {};
    float accB[2][4][4] = {};

    auto load_stage = [&](int ch, int st) {
        const __half *ga, *gb_h, *gb_l;
        if (ch < NCH_S) {
            int tap = ch >> 3;
            int cf0 = (ch & 7) * 32;
            int toff = ((tap / 3) * 58 + (tap % 3)) * 256 + cf0;
            ga   = g_fh + (size_t)ppix * 256 + toff;
            int kt = ch * 32;
            gb_h = g_wsh + lrow * KSPL + kt;
            gb_l = g_wsl + lrow * KSPL + kt;
        } else {
            int tap = ch - NCH_S;
            int toff = ((tap / 3) * 58 + (tap % 3)) * 32;
            ga   = g_xph + (size_t)ppix * 32 + toff;
            int kt = tap * 32;
            gb_h = g_wbh + lrow * KBAS + kt;
            gb_l = g_wbl + lrow * KBAS + kt;
        }
        uint32_t a  = smem_u32(&sA [st][0]) + so0;
        uint32_t bh = smem_u32(&sBh[st][0]) + so0;
        uint32_t bl = smem_u32(&sBl[st][0]) + so0;
#pragma unroll
        for (int s = 0; s < 2; s++) {
            int e = (lsg0 + s) * 8;
            CPA16(a  + s * 16, ga   + e);
            CPA16(bh + s * 16, gb_h + e);
            CPA16(bl + s * 16, gb_l + e);
        }
    };

    auto do_chunk = [&](float (&acc)[2][4][4], int st) {
        const __half* A  = sA [st];
        const __half* Bh = sBh[st];
        const __half* Bl = sBl[st];
#pragma unroll
        for (int k0 = 0; k0 < 32; k0 += 16) {
            uint32_t a[2][4], bh[4][2], bl[4][2];
            const int cb = k0 + 2 * tg;
#pragma unroll
            for (int mi = 0; mi < 2; mi++) {
                int r = wm * 32 + mi * 16 + g;
                a[mi][0] = *(const uint32_t*)&A[r * ASTRIDE + cb];
                a[mi][1] = *(const uint32_t*)&A[(r + 8) * ASTRIDE + cb];
                a[mi][2] = *(const uint32_t*)&A[r * ASTRIDE + cb + 8];
                a[mi][3] = *(const uint32_t*)&A[(r + 8) * ASTRIDE + cb + 8];
            }
#pragma unroll
            for (int nj = 0; nj < 4; nj++) {
                int n = wn * 32 + nj * 8 + g;
                bh[nj][0] = *(const uint32_t*)&Bh[n * ASTRIDE + cb];
                bh[nj][1] = *(const uint32_t*)&Bh[n * ASTRIDE + cb + 8];
                bl[nj][0] = *(const uint32_t*)&Bl[n * ASTRIDE + cb];
                bl[nj][1] = *(const uint32_t*)&Bl[n * ASTRIDE + cb + 8];
            }
#pragma unroll
            for (int mi = 0; mi < 2; mi++)
#pragma unroll
                for (int nj = 0; nj < 4; nj++) {
                    mma16816(acc[mi][nj], a[mi], bh[nj]);
                    mma16816(acc[mi][nj], a[mi], bl[nj]);
                }
        }
    };

    load_stage(chBase, 0);
    CP_COMMIT();
    for (int i = 0; i < CPB; i++) {
        int ch = chBase + i;
        int st = i & 1;
        if (i + 1 < CPB) {
            load_stage(ch + 1, st ^ 1);
            CP_COMMIT();
            CP_WAIT1();
        } else {
            CP_WAIT0();
        }
        __syncthreads();
        if (ch < NCH_S) do_chunk(accS, st);
        else            do_chunk(accB, st);
        __syncthreads();
    }

    // ---- store partials [m][o]; z==2 also stores base result ----
    float* Sp = g_S + (size_t)z * MTOT * 64;
#pragma unroll
    for (int mi = 0; mi < 2; mi++) {
#pragma unroll
        for (int gg = 0; gg < 2; gg++) {
            int row = wm * 32 + mi * 16 + g + gg * 8;
            size_t m = mBase + row;
#pragma unroll
            for (int nj = 0; nj < 4; nj++) {
                int o0 = wn * 32 + nj * 8 + 2 * tg;
                *(float2*)&Sp[m * 64 + o0] =
                    make_float2(accS[mi][nj][gg * 2], accS[mi][nj][gg * 2 + 1]);
                if (z == 2)
                    *(float2*)&g_Bc[m * 64 + o0] =
                        make_float2(accB[mi][nj][gg * 2], accB[mi][nj][gg * 2 + 1]);
            }
        }
    }
}

// ---------------- kernel 4: reduce + silu + scaler epilogue (smem transpose) ----------------
// Block = 64 m-pixels x 64 o. Coalesced float4 reads over o, transpose in smem,
// coalesced float4 writes over m. 3136 = 49*64 -> blocks never straddle images.
__global__ void __launch_bounds__(256) reduce_kernel(const float* __restrict__ scaler,
                                                     float* __restrict__ out)
{
    __shared__ float T[64][65];
    const int tid = threadIdx.x;
    const int mBase = blockIdx.x * 64;
    const int b = mBase / 3136, ssp0 = mBase - b * 3136;

    {   // phase 1: read [m][o] coalesced, compute, store transposed
        const int ml0 = tid >> 4;             // 0..15
        const int o4  = (tid & 15) * 4;
        float4 sc4 = *(const float4*)(scaler + o4);
        const float scv[4] = {sc4.x, sc4.y, sc4.z, sc4.w};
#pragma unroll
        for (int r = 0; r < 4; r++) {
            int ml = ml0 + r * 16;
            size_t m = mBase + ml;
            float4 s0 = *(const float4*)&g_S[m * 64 + o4];
            float4 s1 = *(const float4*)&g_S[((size_t)MTOT + m) * 64 + o4];
            float4 s2 = *(const float4*)&g_S[((size_t)2 * MTOT + m) * 64 + o4];
            float4 bv = *(const float4*)&g_Bc[m * 64 + o4];
            float ss[4] = {s0.x + s1.x + s2.x, s0.y + s1.y + s2.y,
                           s0.z + s1.z + s2.z, s0.w + s1.w + s2.w};
            float bb[4] = {bv.x, bv.y, bv.z, bv.w};
#pragma unroll
            for (int j = 0; j < 4; j++) {
                float silu = bb[j] / (1.0f + expf(-bb[j]));
                T[o4 + j][ml] = silu + scv[j] * ss[j];
            }
        }
    }
    __syncthreads();
    {   // phase 2: write [o][m] coalesced
        const int ol0  = tid >> 4;            // 0..15
        const int mseg = (tid & 15) * 4;
#pragma unroll
        for (int r = 0; r < 4; r++) {
            int o = ol0 + r * 16;
            float4 v = make_float4(T[o][mseg], T[o][mseg + 1], T[o][mseg + 2], T[o][mseg + 3]);
            *(float4*)(out + ((size_t)(b * 64 + o)) * 3136 + ssp0 + mseg) = v;
        }
    }
}

// ---------------- launch ----------------
extern "C" void kernel_launch(void* const* d_in, const int* in_sizes, int n_in,
                              void* d_out, int out_size)
{
    const float* x  = (const float*)d_in[0];  // (4,32,56,56)
    const float* bw = (const float*)d_in[1];  // (64,32,3,3)
    const float* sw = (const float*)d_in[2];  // (64,288,8)
    const float* sc = (const float*)d_in[3];  // (64,)
    float* out = (float*)d_out;               // (4,64,56,56)

    {   // 1. pack weights (fp16 hi/lo, [o][k])
        int total = OUTC * (KSPL + KBAS);
        pack_kernel<<<(total + 255) / 256, 256>>>(sw, bw);
    }
    {   // 2. basis expansion over the padded grid
        int total = NPIX * 32;
        fillpad_kernel<<<(total + 255) / 256, 256>>>(x);
    }
    {   // 3. split-K GEMM: 588 uniform blocks (~3.97/SM)
        dim3 grid(MTOT / 64, 3);
        kan_mma_kernel<<<grid, 128>>>();
    }
    {   // 4. reduce + silu + scaler + store (transposed, coalesced)
        reduce_kernel<<<MTOT / 64, 256>>>(sc, out);
    }
}